// round 11
// baseline (speedup 1.0000x reference)
#include <cuda_runtime.h>

// y[b,s,d] = x[b,s,d] * gain[d]
// gain[d]  = sum_n cos(n*w*dt - eps[n,d]*dt),  eps = fe*(1+0.1*dw[n]), w=1, dt=0.01
//
// Reduction (validated, rel_err 4.1e-8): b = eps*dt ~ 1e-4,
//   cos(a_n - b) ~= cos a_n + sin a_n*b - 0.5 cos a_n*b^2
//   gain = C0 + sum_n (p_n + q_n*f)*f
// M==16 fully unrolled => cosf/sinf constant-fold => no MUFU.
//
// R11: fe prologue traffic = total_threads * 256 B. Final halving: 148 blocks
// (1 CTA/SM, 8 warps) -> 9.7 MB fe burst, zero wave imbalance. Stream MLP held
// by unroll-8 batch (8 warps * 8 * 512 B = 32 KB read-side in flight per SM,
// ~4x the ~8 KB latency-BW product). launch_bounds(256,1) -> full reg budget.
// Grid stride S = 148*256 = 37888 float4, multiple of D/4=1024 -> per-thread
// d-position loop-invariant; gain lives in 4 registers.

__global__ void __launch_bounds__(256, 1) fused_kernel(
    const float4* __restrict__ x, float4* __restrict__ out,
    const float* __restrict__ fe, const float* __restrict__ dw,
    int M, int n4, unsigned d4mask)
{
    const int i0 = blockIdx.x * blockDim.x + threadIdx.x;
    const int S  = gridDim.x * blockDim.x;
    const unsigned dq = (unsigned)i0 & d4mask;       // float4-group within D
    const int D4 = (int)(d4mask + 1u);
    const float4* fe4 = reinterpret_cast<const float4*>(fe);

    // ---- Prefetch stream head: overlaps the fe/L2 burst with x DRAM latency.
    const bool h0 = (i0 < n4);
    const bool h1 = (i0 + S < n4);
    const bool h2 = (i0 + 2 * S < n4);
    float4 v0, v1, v2;
    if (h0) v0 = x[i0];
    if (h1) v1 = x[i0 + S];
    if (h2) v2 = x[i0 + 2 * S];

    float gx, gy, gz, gw;

    if (M == 16) {
        const float4* dw4 = reinterpret_cast<const float4*>(dw);
        float w[16];
        #pragma unroll
        for (int k = 0; k < 4; k++) {
            float4 t = __ldg(&dw4[k]);
            w[4*k+0] = t.x; w[4*k+1] = t.y; w[4*k+2] = t.z; w[4*k+3] = t.w;
        }
        float c0 = 0.f;
        gx = gy = gz = gw = 0.f;
        #pragma unroll
        for (int n = 0; n < 16; n++) {
            const float a  = (float)n * 0.01f;        // literal per unrolled iter
            const float ca = cosf(a);                 // constant-folded
            const float sa = sinf(a);                 // constant-folded
            c0 += ca;
            float scl = fmaf(0.1f, w[n], 1.0f) * 0.01f;
            float p = sa * scl;
            float q = -0.5f * ca * scl * scl;
            float4 f = __ldg(&fe4[n * D4 + dq]);
            gx = fmaf(fmaf(q, f.x, p), f.x, gx);
            gy = fmaf(fmaf(q, f.y, p), f.y, gy);
            gz = fmaf(fmaf(q, f.z, p), f.z, gz);
            gw = fmaf(fmaf(q, f.w, p), f.w, gw);
        }
        gx += c0; gy += c0; gz += c0; gw += c0;
    } else {
        gx = gy = gz = gw = 0.f;
        for (int n = 0; n < M; n++) {
            float a  = (float)n * 0.01f;
            float ca = cosf(a), sa = sinf(a);
            float scl = fmaf(0.1f, __ldg(&dw[n]), 1.0f) * 0.01f;
            float p = sa * scl;
            float q = -0.5f * ca * scl * scl;
            float4 f = __ldg(&fe4[n * D4 + dq]);
            gx = fmaf(fmaf(q, f.x, p), f.x, gx + ca);
            gy = fmaf(fmaf(q, f.y, p), f.y, gy + ca);
            gz = fmaf(fmaf(q, f.z, p), f.z, gz + ca);
            gw = fmaf(fmaf(q, f.w, p), f.w, gw + ca);
        }
    }

    // ---- Drain the prefetched head ----
    if (h0) { v0.x *= gx; v0.y *= gy; v0.z *= gz; v0.w *= gw; out[i0] = v0; }
    if (h1) { v1.x *= gx; v1.y *= gy; v1.z *= gz; v1.w *= gw; out[i0 + S] = v1; }
    if (h2) { v2.x *= gx; v2.y *= gy; v2.z *= gz; v2.w *= gw; out[i0 + 2 * S] = v2; }

    // ---- Unroll-8 batched streaming loop (8 independent loads in flight) ----
    int i = i0 + 3 * S;
    for (; i + 7 * S < n4; i += 8 * S) {
        float4 a0 = x[i];
        float4 a1 = x[i + S];
        float4 a2 = x[i + 2 * S];
        float4 a3 = x[i + 3 * S];
        float4 a4 = x[i + 4 * S];
        float4 a5 = x[i + 5 * S];
        float4 a6 = x[i + 6 * S];
        float4 a7 = x[i + 7 * S];
        a0.x *= gx; a0.y *= gy; a0.z *= gz; a0.w *= gw;
        a1.x *= gx; a1.y *= gy; a1.z *= gz; a1.w *= gw;
        a2.x *= gx; a2.y *= gy; a2.z *= gz; a2.w *= gw;
        a3.x *= gx; a3.y *= gy; a3.z *= gz; a3.w *= gw;
        a4.x *= gx; a4.y *= gy; a4.z *= gz; a4.w *= gw;
        a5.x *= gx; a5.y *= gy; a5.z *= gz; a5.w *= gw;
        a6.x *= gx; a6.y *= gy; a6.z *= gz; a6.w *= gw;
        a7.x *= gx; a7.y *= gy; a7.z *= gz; a7.w *= gw;
        out[i]         = a0;
        out[i + S]     = a1;
        out[i + 2 * S] = a2;
        out[i + 3 * S] = a3;
        out[i + 4 * S] = a4;
        out[i + 5 * S] = a5;
        out[i + 6 * S] = a6;
        out[i + 7 * S] = a7;
    }
    for (; i < n4; i += S) {
        float4 v = x[i];
        v.x *= gx; v.y *= gy; v.z *= gz; v.w *= gw;
        out[i] = v;
    }
}

// ---------------- fallback path (generic shapes) ----------------
#define MAX_D 8192
__device__ float g_gain[MAX_D];

__global__ void __launch_bounds__(128) gain_kernel(const float* __restrict__ fe,
                                                   const float* __restrict__ dw,
                                                   int M, int D) {
    int d = blockIdx.x * blockDim.x + threadIdx.x;
    if (d >= D) return;
    float s = 0.0f;
    for (int n = 0; n < M; n++) {
        float a = (float)n * 0.01f;
        float b = fe[n * D + d] * (fmaf(0.1f, dw[n], 1.0f) * 0.01f);
        s += fmaf(sinf(a), b, cosf(a)) - 0.5f * cosf(a) * b * b;
    }
    g_gain[d] = s;
}

__global__ void __launch_bounds__(256) scale_kernel_mod(const float4* __restrict__ x,
                                                        float4* __restrict__ out,
                                                        int n4, int d4) {
    int S = gridDim.x * blockDim.x;
    for (int i = blockIdx.x * blockDim.x + threadIdx.x; i < n4; i += S) {
        int r = i % d4;
        float4 g = *reinterpret_cast<const float4*>(&g_gain[r * 4]);
        float4 v = x[i];
        v.x *= g.x; v.y *= g.y; v.z *= g.z; v.w *= g.w;
        out[i] = v;
    }
}

extern "C" void kernel_launch(void* const* d_in, const int* in_sizes, int n_in,
                              void* d_out, int out_size) {
    const float* x  = (const float*)d_in[0];   // [B, S, D]
    const float* fe = (const float*)d_in[1];   // [M, D]
    const float* dw = (const float*)d_in[2];   // [M]
    // d_in[3] = coupling_matrix, unused by the reference forward.

    int M = in_sizes[2];
    int D = in_sizes[1] / M;
    int total = out_size;          // B*S*D
    int n4 = total / 4;
    int d4 = D / 4;

    bool pow2 = (D % 4 == 0) && ((d4 & (d4 - 1)) == 0);

    int threads = 256;
    int blocks = 148;              // R11: 1 CTA/SM -> fe prologue 9.7 MB
    int need = (n4 + threads - 1) / threads;
    if (blocks > need) blocks = need;
    bool stride_ok = pow2 && ((blocks * threads) % d4 == 0);

    if (stride_ok) {
        fused_kernel<<<blocks, threads>>>((const float4*)x, (float4*)d_out,
                                          fe, dw, M, n4, (unsigned)(d4 - 1));
    } else {
        gain_kernel<<<(D + 127) / 128, 128>>>(fe, dw, M, D);
        int sblocks = 148 * 8;
        if (sblocks > need) sblocks = need;
        scale_kernel_mod<<<sblocks, threads>>>((const float4*)x, (float4*)d_out,
                                               n4, d4);
    }
}

// round 13
// speedup vs baseline: 1.1369x; 1.1369x over previous
#include <cuda_runtime.h>

// y[b,s,d] = x[b,s,d] * gain[d]
// gain[d]  = sum_n cos(n*w*dt - eps[n,d]*dt),  eps = fe*(1+0.1*dw[n]), w=1, dt=0.01
//
// Reduction (validated, rel_err 4.1e-8): b = eps*dt ~ 1e-4,
//   cos(a_n - b) ~= cos a_n + sin a_n*b - 0.5 cos a_n*b^2
//   gain = C0 + sum_n (p_n + q_n*f)*f
// M==16 fully unrolled => cosf/sinf constant-fold => no MUFU.
//
// R12 = R10 champion config (296 blocks = 2 CTAs/SM, unroll-6 batch, proven
// 79.55us @ DRAM 77.2%) + ONE change: __stcs on the output stores. out is
// write-once/never-read; evict-first store lines stop displacing the x read
// stream in L2. (R5's .cs regression was confounded: hints on loads too +
// 4x gain lookups. This isolates store-side.)
// Grid stride S = 296*256 = 75776 float4, multiple of D/4=1024 -> per-thread
// d-position loop-invariant; gain lives in 4 registers.

__global__ void __launch_bounds__(256, 2) fused_kernel(
    const float4* __restrict__ x, float4* __restrict__ out,
    const float* __restrict__ fe, const float* __restrict__ dw,
    int M, int n4, unsigned d4mask)
{
    const int i0 = blockIdx.x * blockDim.x + threadIdx.x;
    const int S  = gridDim.x * blockDim.x;
    const unsigned dq = (unsigned)i0 & d4mask;       // float4-group within D
    const int D4 = (int)(d4mask + 1u);
    const float4* fe4 = reinterpret_cast<const float4*>(fe);

    // ---- Prefetch stream head: overlaps the fe/L2 burst with x DRAM latency.
    const bool h0 = (i0 < n4);
    const bool h1 = (i0 + S < n4);
    const bool h2 = (i0 + 2 * S < n4);
    float4 v0, v1, v2;
    if (h0) v0 = x[i0];
    if (h1) v1 = x[i0 + S];
    if (h2) v2 = x[i0 + 2 * S];

    float gx, gy, gz, gw;

    if (M == 16) {
        const float4* dw4 = reinterpret_cast<const float4*>(dw);
        float w[16];
        #pragma unroll
        for (int k = 0; k < 4; k++) {
            float4 t = __ldg(&dw4[k]);
            w[4*k+0] = t.x; w[4*k+1] = t.y; w[4*k+2] = t.z; w[4*k+3] = t.w;
        }
        float c0 = 0.f;
        gx = gy = gz = gw = 0.f;
        #pragma unroll
        for (int n = 0; n < 16; n++) {
            const float a  = (float)n * 0.01f;        // literal per unrolled iter
            const float ca = cosf(a);                 // constant-folded
            const float sa = sinf(a);                 // constant-folded
            c0 += ca;
            float scl = fmaf(0.1f, w[n], 1.0f) * 0.01f;
            float p = sa * scl;
            float q = -0.5f * ca * scl * scl;
            float4 f = __ldg(&fe4[n * D4 + dq]);
            gx = fmaf(fmaf(q, f.x, p), f.x, gx);
            gy = fmaf(fmaf(q, f.y, p), f.y, gy);
            gz = fmaf(fmaf(q, f.z, p), f.z, gz);
            gw = fmaf(fmaf(q, f.w, p), f.w, gw);
        }
        gx += c0; gy += c0; gz += c0; gw += c0;
    } else {
        gx = gy = gz = gw = 0.f;
        for (int n = 0; n < M; n++) {
            float a  = (float)n * 0.01f;
            float ca = cosf(a), sa = sinf(a);
            float scl = fmaf(0.1f, __ldg(&dw[n]), 1.0f) * 0.01f;
            float p = sa * scl;
            float q = -0.5f * ca * scl * scl;
            float4 f = __ldg(&fe4[n * D4 + dq]);
            gx = fmaf(fmaf(q, f.x, p), f.x, gx + ca);
            gy = fmaf(fmaf(q, f.y, p), f.y, gy + ca);
            gz = fmaf(fmaf(q, f.z, p), f.z, gz + ca);
            gw = fmaf(fmaf(q, f.w, p), f.w, gw + ca);
        }
    }

    // ---- Drain the prefetched head ----
    if (h0) { v0.x *= gx; v0.y *= gy; v0.z *= gz; v0.w *= gw; __stcs(&out[i0], v0); }
    if (h1) { v1.x *= gx; v1.y *= gy; v1.z *= gz; v1.w *= gw; __stcs(&out[i0 + S], v1); }
    if (h2) { v2.x *= gx; v2.y *= gy; v2.z *= gz; v2.w *= gw; __stcs(&out[i0 + 2 * S], v2); }

    // ---- Unroll-6 batched streaming loop (6 independent loads in flight) ----
    int i = i0 + 3 * S;
    for (; i + 5 * S < n4; i += 6 * S) {
        float4 a0 = x[i];
        float4 a1 = x[i + S];
        float4 a2 = x[i + 2 * S];
        float4 a3 = x[i + 3 * S];
        float4 a4 = x[i + 4 * S];
        float4 a5 = x[i + 5 * S];
        a0.x *= gx; a0.y *= gy; a0.z *= gz; a0.w *= gw;
        a1.x *= gx; a1.y *= gy; a1.z *= gz; a1.w *= gw;
        a2.x *= gx; a2.y *= gy; a2.z *= gz; a2.w *= gw;
        a3.x *= gx; a3.y *= gy; a3.z *= gz; a3.w *= gw;
        a4.x *= gx; a4.y *= gy; a4.z *= gz; a4.w *= gw;
        a5.x *= gx; a5.y *= gy; a5.z *= gz; a5.w *= gw;
        __stcs(&out[i],         a0);
        __stcs(&out[i + S],     a1);
        __stcs(&out[i + 2 * S], a2);
        __stcs(&out[i + 3 * S], a3);
        __stcs(&out[i + 4 * S], a4);
        __stcs(&out[i + 5 * S], a5);
    }
    for (; i < n4; i += S) {
        float4 v = x[i];
        v.x *= gx; v.y *= gy; v.z *= gz; v.w *= gw;
        __stcs(&out[i], v);
    }
}

// ---------------- fallback path (generic shapes) ----------------
#define MAX_D 8192
__device__ float g_gain[MAX_D];

__global__ void __launch_bounds__(128) gain_kernel(const float* __restrict__ fe,
                                                   const float* __restrict__ dw,
                                                   int M, int D) {
    int d = blockIdx.x * blockDim.x + threadIdx.x;
    if (d >= D) return;
    float s = 0.0f;
    for (int n = 0; n < M; n++) {
        float a = (float)n * 0.01f;
        float b = fe[n * D + d] * (fmaf(0.1f, dw[n], 1.0f) * 0.01f);
        s += fmaf(sinf(a), b, cosf(a)) - 0.5f * cosf(a) * b * b;
    }
    g_gain[d] = s;
}

__global__ void __launch_bounds__(256) scale_kernel_mod(const float4* __restrict__ x,
                                                        float4* __restrict__ out,
                                                        int n4, int d4) {
    int S = gridDim.x * blockDim.x;
    for (int i = blockIdx.x * blockDim.x + threadIdx.x; i < n4; i += S) {
        int r = i % d4;
        float4 g = *reinterpret_cast<const float4*>(&g_gain[r * 4]);
        float4 v = x[i];
        v.x *= g.x; v.y *= g.y; v.z *= g.z; v.w *= g.w;
        out[i] = v;
    }
}

extern "C" void kernel_launch(void* const* d_in, const int* in_sizes, int n_in,
                              void* d_out, int out_size) {
    const float* x  = (const float*)d_in[0];   // [B, S, D]
    const float* fe = (const float*)d_in[1];   // [M, D]
    const float* dw = (const float*)d_in[2];   // [M]
    // d_in[3] = coupling_matrix, unused by the reference forward.

    int M = in_sizes[2];
    int D = in_sizes[1] / M;
    int total = out_size;          // B*S*D
    int n4 = total / 4;
    int d4 = D / 4;

    bool pow2 = (D % 4 == 0) && ((d4 & (d4 - 1)) == 0);

    int threads = 256;
    int blocks = 148 * 2;          // R10-proven optimum: 2 CTAs/SM
    int need = (n4 + threads - 1) / threads;
    if (blocks > need) blocks = need;
    bool stride_ok = pow2 && ((blocks * threads) % d4 == 0);

    if (stride_ok) {
        fused_kernel<<<blocks, threads>>>((const float4*)x, (float4*)d_out,
                                          fe, dw, M, n4, (unsigned)(d4 - 1));
    } else {
        gain_kernel<<<(D + 127) / 128, 128>>>(fe, dw, M, D);
        int sblocks = 148 * 8;
        if (sblocks > need) sblocks = need;
        scale_kernel_mod<<<sblocks, threads>>>((const float4*)x, (float4*)d_out,
                                               n4, d4);
    }
}